// round 16
// baseline (speedup 1.0000x reference)
#include <cuda_runtime.h>
#include <cfloat>

// Symmetric squared-Hausdorff per batch — single persistent kernel (R16).
// d^2(p,g) = |p|^2 + s, s = |g|^2 - 2 p.g (|p|^2 added after the min).
//
// Grid = 512 blocks x 256 threads, __launch_bounds__(256,4) => <=64 regs =>
// 4 blocks/SM capacity => all 512 co-resident (grid barrier safe), 32 warps/SM.
// Phase A: pack both arrays (-2g,|g|^2), 256 pts/block, per-chunk radius
//          argmax (16 chunks per (arr,b)) + resets.       [grid barrier]
// Phase B: per (dir,b,och: 16): candidate = best of 16 chunk candidates;
//          16-way distributed LB (1 eval/thread, atomicMin-combined);
//          branchless f32x2 scan of first 128 inner pts (1 pt/thread);
//          poll LB counter (==16); certified -> block max atomicMax;
//          uncertified -> global list.                    [grid barrier]
// Phase C: 4096 warps work-steal list entries (atomic ticket); one point/warp:
//          half-round [128,256) + vote, then 15 x 256-pt vote rounds over
//          [256,4096) (divides evenly — no OOB); exact values atomicMax'ed.
//          Done-ticket: last block writes out[16].
//
// Exactness: certified partials lie in [true, LB) and cannot win the max;
// the argmax never certifies and its exact min is computed from identically-
// evaluated per-pair values. All combines (min/max/atomicMin/atomicMax) are
// order-independent -> deterministic.

#define BATCH   16
#define NPTS    4096
#define NBLK    512
#define T       256
#define PCH     16                   // pack chunks per (arr,b)
#define PTSBLK  T                    // 256 outer pts per phase-B block
#define OCH     16
#define P1PTS   128                  // phase-1 inner points
#define P1SLOTS (P1PTS / 2)          // 64 packed pair-slots
#define TAIL0   256                  // start of evenly-divisible tail region
#define VC      8                    // tail lane-iters per vote round (256 pts)

__device__ float4       g_pack[2][BATCH][NPTS];     // (-2gx,-2gy,-2gz,|g|^2)
__device__ float4       g_candpart[2][BATCH][PCH];  // (cx,cy,cz,|c|^2)
__device__ unsigned int g_lbmin_u[2][BATCH];        // encoded min (s-domain)
__device__ unsigned int g_lbc[2][BATCH];            // LB arrival counter
__device__ float        g_lb[2][BATCH];             // final LB (with margin)
__device__ int2         g_list[2 * BATCH * NPTS];   // (code, partial bits)
__device__ int          g_cnt;
__device__ int          g_ticket;
__device__ unsigned int g_done;
__device__ unsigned int g_bar[2];                   // generation barriers
__device__ unsigned int g_bmax_u[2][BATCH];         // monotonic-encoded max

typedef unsigned long long u64t;

__device__ __forceinline__ u64t fma2(u64t a, u64t b, u64t c) {
    u64t d;
    asm("fma.rn.f32x2 %0, %1, %2, %3;" : "=l"(d) : "l"(a), "l"(b), "l"(c));
    return d;
}
__device__ __forceinline__ u64t pk(float lo, float hi) {
    u64t d;
    asm("mov.b64 %0, {%1, %2};" : "=l"(d) : "f"(lo), "f"(hi));
    return d;
}
__device__ __forceinline__ float2 upk(u64t v) {
    float2 r;
    asm("mov.b64 {%0, %1}, %2;" : "=f"(r.x), "=f"(r.y) : "l"(v));
    return r;
}
// monotonic float<->uint (total order preserved under unsigned compare)
__device__ __forceinline__ unsigned int encf(float v) {
    unsigned int b = __float_as_uint(v);
    return (b & 0x80000000u) ? ~b : (b | 0x80000000u);
}
__device__ __forceinline__ float decf(unsigned int u) {
    unsigned int b = (u & 0x80000000u) ? (u & 0x7fffffffu) : ~u;
    return __uint_as_float(b);
}
__device__ __forceinline__ unsigned int ldacq(const unsigned int* p) {
    unsigned int v;
    asm volatile("ld.acquire.gpu.u32 %0, [%1];" : "=r"(v) : "l"(p) : "memory");
    return v;
}

// generation-counting grid barrier; poll is a plain acquire load. Counter is
// monotonic -> safe across graph replays. All NBLK blocks are co-resident.
__device__ __forceinline__ void gbar(int which) {
    __threadfence();
    __syncthreads();
    if (threadIdx.x == 0) {
        unsigned int gen = atomicAdd(&g_bar[which], 1u) / NBLK;
        while (ldacq(&g_bar[which]) / NBLK == gen) { }
    }
    __syncthreads();
}

__global__ void __launch_bounds__(T, 4)
hd_fused(const float* __restrict__ preds, const float* __restrict__ gts,
         float* __restrict__ out) {
    __shared__ __align__(16) ulonglong2 shv[P1SLOTS * 2];   // 2 KB
    __shared__ float s_red[T / 32];
    __shared__ int   s_redi[T / 32];
    __shared__ float s_lb;
    __shared__ bool  s_last;

    const int bid = blockIdx.x;
    const int tid = threadIdx.x;
    const int lane = tid & 31;

    // ================= Phase A: pack + chunk candidates + resets ===========
    {
        const int arr = bid >> 8, b = (bid >> 4) & 15, ch = bid & 15;
        const float* __restrict__ src = (arr == 0 ? preds : gts) + (size_t)b * NPTS * 3;
        const int j = ch * (NPTS / PCH) + tid;        // 256 pts / block

        if (tid == 0 && ch == 0) {
            g_bmax_u[arr][b]  = 0u;
            g_lbmin_u[arr][b] = 0xFFFFFFFFu;
            g_lbc[arr][b]     = 0u;
            if (bid == 0) { g_cnt = 0; g_ticket = 0; g_done = 0u; }
        }

        float gx = src[3*j], gy = src[3*j+1], gz = src[3*j+2];
        float w  = fmaf(gx, gx, fmaf(gy, gy, gz * gz));
        g_pack[arr][b][j] = make_float4(-2.0f*gx, -2.0f*gy, -2.0f*gz, w);

        float bestr = w; int besti = j;
#pragma unroll
        for (int off = 16; off; off >>= 1) {
            float r2 = __shfl_xor_sync(0xffffffffu, bestr, off);
            int   i2 = __shfl_xor_sync(0xffffffffu, besti, off);
            if (r2 > bestr || (r2 == bestr && i2 < besti)) { bestr = r2; besti = i2; }
        }
        if (lane == 0) { s_red[tid>>5] = bestr; s_redi[tid>>5] = besti; }
        __syncthreads();
        if (tid == 0) {
            float r = s_red[0]; int i = s_redi[0];
#pragma unroll
            for (int w2 = 1; w2 < T/32; w2++)
                if (s_red[w2] > r || (s_red[w2] == r && s_redi[w2] < i)) { r = s_red[w2]; i = s_redi[w2]; }
            g_candpart[arr][b][ch] = make_float4(src[3*i], src[3*i+1], src[3*i+2], r);
        }
        __syncthreads();
    }
    gbar(0);

    // ================= Phase B: distributed LB + branchless p1 + filter =====
    {
        const int dir = bid >> 8, b = (bid >> 4) & 15, och = bid & 15;
        const float* __restrict__ outer = (dir == 0 ? preds : gts) + (size_t)b * NPTS * 3;
        const float* __restrict__ inner = (dir == 0 ? gts : preds) + (size_t)b * NPTS * 3;
        const float4* __restrict__ packp = &g_pack[dir ^ 1][b][0];

        // stage first P1SLOTS pairs (threads 0..63)
        if (tid < P1SLOTS) {
            const float* gp = inner + (size_t)tid * 6;
            float x0 = gp[0], y0 = gp[1], z0 = gp[2];
            float x1 = gp[3], y1 = gp[4], z1 = gp[5];
            ((float4*)shv)[tid * 2 + 0] = make_float4(-2.f*x0, -2.f*x1, -2.f*y0, -2.f*y1);
            ((float4*)shv)[tid * 2 + 1] = make_float4(-2.f*z0, -2.f*z1,
                                    fmaf(x0, x0, fmaf(y0, y0, z0*z0)),
                                    fmaf(x1, x1, fmaf(y1, y1, z1*z1)));
        }

        // candidate = best of 16 chunk candidates (deterministic ascending scan)
        float4 cand = g_candpart[dir][b][0];
#pragma unroll
        for (int c = 1; c < PCH; c++) {
            float4 q = g_candpart[dir][b][c];
            if (q.w > cand.w) cand = q;
        }

        const int gi0 = och * PTSBLK + tid;          // this thread's outer pt
        float px = outer[3*gi0], py = outer[3*gi0+1], pz = outer[3*gi0+2];
        const u64t px2 = pk(px, px), py2 = pk(py, py), pz2 = pk(pz, pz);
        const float rq = fmaf(px, px, fmaf(py, py, pz*pz));
        float mn = FLT_MAX;

        // distributed LB: candidate vs this block's 1/16 of the inner pack
        float cm;
        {
            float4 p = packp[och * PTSBLK + tid];    // 1 eval/thread
            float t = fmaf(p.x, cand.x, p.w);
            t = fmaf(p.y, cand.y, t);
            cm = fmaf(p.z, cand.z, t);
        }
#pragma unroll
        for (int off = 16; off; off >>= 1)
            cm = fminf(cm, __shfl_xor_sync(0xffffffffu, cm, off));
        if (lane == 0) s_red[tid >> 5] = cm;
        __syncthreads();                              // also: staging visible
        if (tid == 0) {
            float m = s_red[0];
#pragma unroll
            for (int w = 1; w < T / 32; w++) m = fminf(m, s_red[w]);
            atomicMin(&g_lbmin_u[dir][b], encf(m));
            __threadfence();
            atomicAdd(&g_lbc[dir][b], 1u);
        }

        // branchless phase-1 scan (64 slots = 128 pts), 2 slots interleaved
#pragma unroll 4
        for (int s = 0; s < P1SLOTS; s += 2) {
            ulonglong2 ab0 = shv[s * 2 + 0];
            ulonglong2 cd0 = shv[s * 2 + 1];
            ulonglong2 ab1 = shv[s * 2 + 2];
            ulonglong2 cd1 = shv[s * 2 + 3];
            u64t t0 = fma2(ab0.x, px2, cd0.y);
            u64t t1 = fma2(ab1.x, px2, cd1.y);
            t0 = fma2(ab0.y, py2, t0);
            t1 = fma2(ab1.y, py2, t1);
            t0 = fma2(cd0.x, pz2, t0);
            t1 = fma2(cd1.x, pz2, t1);
            float2 v0 = upk(t0), v1 = upk(t1);
            mn = fminf(mn, fminf(fminf(v0.x, v0.y), fminf(v1.x, v1.y)));
        }

        // collect the combined LB (16 contributions normally long done)
        if (tid == 0) {
            while (ldacq(&g_lbc[dir][b]) < OCH) { }
            float lb = decf(ldacq(&g_lbmin_u[dir][b])) + cand.w;
            s_lb = lb - fabsf(lb) * 1e-5f - 1e-12f;
            if (och == 0) g_lb[dir][b] = s_lb;       // identical in all blocks
        }
        __syncthreads();

        // filter: certified -> block max; uncertified -> global list
        const float lbm = s_lb;
        float v = mn + rq;
        float cmax = -FLT_MAX;
        if (v < lbm) {
            cmax = v;
        } else {
            int k = atomicAdd(&g_cnt, 1);
            g_list[k] = make_int2((dir << 16) | (b << 12) | gi0,
                                  __float_as_int(v));
        }
#pragma unroll
        for (int off = 16; off; off >>= 1)
            cmax = fmaxf(cmax, __shfl_xor_sync(0xffffffffu, cmax, off));
        if (lane == 0) s_red[tid >> 5] = cmax;
        __syncthreads();
        if (tid == 0) {
            float m = s_red[0];
#pragma unroll
            for (int w = 1; w < T / 32; w++) m = fmaxf(m, s_red[w]);
            atomicMax(&g_bmax_u[dir][b], encf(m));
        }
    }
    gbar(1);

    // ================= Phase C: work-stealing warp-per-point tail ===========
    {
        const int cnt = g_cnt;
        int u;
        if (lane == 0) u = atomicAdd(&g_ticket, 1);
        u = __shfl_sync(0xffffffffu, u, 0);
        while (u < cnt) {
            const int2 e = g_list[u];
            const int code = e.x;
            const float partial = __int_as_float(e.y);
            const int gi = code & 4095, b = (code >> 12) & 15, dir = code >> 16;
            const float* __restrict__ outer = (dir == 0 ? preds : gts) + (size_t)b * NPTS * 3;

            const float x = outer[3*gi], y = outer[3*gi+1], z = outer[3*gi+2];
            const float rq = fmaf(x, x, fmaf(y, y, z*z));
            const float thr = g_lb[dir][b] - rq;     // s-domain threshold
            const float4* packp = &g_pack[dir ^ 1][b][0];

            float m = FLT_MAX;
            // half round: inner points [P1PTS, TAIL0) = 128 pts (4 lane-iters)
#pragma unroll
            for (int k = 0; k < (TAIL0 - P1PTS) / 32; k++) {
                float4 p = packp[P1PTS + k * 32 + lane];
                float t = fmaf(p.x, x, p.w);
                t = fmaf(p.y, y, t);
                t = fmaf(p.z, z, t);
                m = fminf(m, t);
            }
            if (!__any_sync(0xffffffffu, m < thr)) {
                // full rounds: [TAIL0, NPTS) = 3840 pts = 15 rounds of 256
                for (int base = TAIL0; base < NPTS; base += 32 * VC) {
#pragma unroll
                    for (int k = 0; k < VC; k++) {
                        float4 p = packp[base + k * 32 + lane];
                        float t = fmaf(p.x, x, p.w);
                        t = fmaf(p.y, y, t);
                        t = fmaf(p.z, z, t);
                        m = fminf(m, t);
                    }
                    if (__any_sync(0xffffffffu, m < thr)) break;   // certified
                }
            }
#pragma unroll
            for (int off = 16; off; off >>= 1)
                m = fminf(m, __shfl_xor_sync(0xffffffffu, m, off));
            if (lane == 0)
                atomicMax(&g_bmax_u[dir][b], encf(fminf(partial, m + rq)));

            if (lane == 0) u = atomicAdd(&g_ticket, 1);
            u = __shfl_sync(0xffffffffu, u, 0);
        }
    }

    // ================= done-ticket final: last block writes out =============
    __threadfence();
    __syncthreads();
    if (tid == 0) {
        unsigned int t = atomicAdd(&g_done, 1u);
        s_last = ((t % NBLK) == NBLK - 1);
    }
    __syncthreads();
    if (s_last && tid < BATCH) {
        float l2 = decf(ldacq(&g_bmax_u[0][tid]));
        float l1 = decf(ldacq(&g_bmax_u[1][tid]));
        out[tid] = 0.5f * (l1 + l2);
    }
}

extern "C" void kernel_launch(void* const* d_in, const int* in_sizes, int n_in,
                              void* d_out, int out_size) {
    const float* preds = (const float*)d_in[0];
    const float* gts   = (const float*)d_in[1];
    float* out = (float*)d_out;

    hd_fused<<<NBLK, T>>>(preds, gts, out);
}